// round 10
// baseline (speedup 1.0000x reference)
#include <cuda_runtime.h>
#include <cstdint>

#define BB 64
#define MM 2048
#define DD 512
#define ROWS_PER_BLOCK 8
#define CHUNKS_PER_B (MM / ROWS_PER_BLOCK)   // 256
#define WARPS_PER_BLOCK 8

// Per-(batch, chunk) partial: high 32 = float bits of squared distance
// (non-negative -> monotone bit pattern), low 32 = (MM-1-idx) so ties pick the
// SMALLEST index under max (matches jnp.argmax first-occurrence).
__device__ unsigned long long g_part[BB * CHUNKS_PER_B];
// Per-batch arrival counter; zero-initialized at load, reset by the finishing
// block so every graph replay starts clean.
__device__ int g_cnt[BB];

__global__ __launch_bounds__(256, 5) void knn_nosync_kernel(
    const float* __restrict__ inputs,   // [BB, DD]
    const float* __restrict__ buffer,   // [BB, MM, DD]
    float* __restrict__ out)            // [BB, DD]
{
    __shared__ unsigned long long s_warp_best[WARPS_PER_BLOCK];
    __shared__ int s_idx;

    const int b     = blockIdx.x >> 8;                 // / CHUNKS_PER_B
    const int chunk = blockIdx.x & (CHUNKS_PER_B - 1);

    const int warp = threadIdx.x >> 5;
    const int lane = threadIdx.x & 31;
    const int m    = chunk * ROWS_PER_BLOCK + warp;    // this warp's row

    const float4* row = reinterpret_cast<const float4*>(
        buffer + ((size_t)b * MM + (size_t)m) * DD);
    const float4* qp = reinterpret_cast<const float4*>(inputs + (size_t)b * DD);

    // Batch ALL 8 loads (4 DRAM row + 4 L2-resident query) with no barrier in
    // front of them: the block starts streaming the moment it lands on the SM.
    float4 v0 = __ldg(row + lane);
    float4 v1 = __ldg(row + lane + 32);
    float4 v2 = __ldg(row + lane + 64);
    float4 v3 = __ldg(row + lane + 96);
    float4 q0 = __ldg(qp + lane);
    float4 q1 = __ldg(qp + lane + 32);
    float4 q2 = __ldg(qp + lane + 64);
    float4 q3 = __ldg(qp + lane + 96);

    float acc = 0.0f;
    {
        float dx = v0.x - q0.x, dy = v0.y - q0.y, dz = v0.z - q0.z, dw = v0.w - q0.w;
        acc = fmaf(dx, dx, acc); acc = fmaf(dy, dy, acc);
        acc = fmaf(dz, dz, acc); acc = fmaf(dw, dw, acc);
        dx = v1.x - q1.x; dy = v1.y - q1.y; dz = v1.z - q1.z; dw = v1.w - q1.w;
        acc = fmaf(dx, dx, acc); acc = fmaf(dy, dy, acc);
        acc = fmaf(dz, dz, acc); acc = fmaf(dw, dw, acc);
        dx = v2.x - q2.x; dy = v2.y - q2.y; dz = v2.z - q2.z; dw = v2.w - q2.w;
        acc = fmaf(dx, dx, acc); acc = fmaf(dy, dy, acc);
        acc = fmaf(dz, dz, acc); acc = fmaf(dw, dw, acc);
        dx = v3.x - q3.x; dy = v3.y - q3.y; dz = v3.z - q3.z; dw = v3.w - q3.w;
        acc = fmaf(dx, dx, acc); acc = fmaf(dy, dy, acc);
        acc = fmaf(dz, dz, acc); acc = fmaf(dw, dw, acc);
    }

    // Warp tree-reduce the row distance.
#pragma unroll
    for (int o = 16; o > 0; o >>= 1)
        acc += __shfl_xor_sync(0xFFFFFFFFu, acc, o);

    if (lane == 0) {
        s_warp_best[warp] =
            ((unsigned long long)__float_as_uint(acc) << 32) |
            (unsigned int)(MM - 1 - m);
    }
    __syncthreads();

    if (threadIdx.x == 0) {
        unsigned long long blk = 0ULL;
#pragma unroll
        for (int w = 0; w < WARPS_PER_BLOCK; w++)
            blk = max(blk, s_warp_best[w]);
        g_part[b * CHUNKS_PER_B + chunk] = blk;
        __threadfence();
        int arrived = atomicAdd(&g_cnt[b], 1);
        s_idx = (arrived == CHUNKS_PER_B - 1) ? 1 : 0;
    }
    __syncthreads();

    // Last-arriving block of this batch: reduce 256 partials + gather.
    if (s_idx) {
        if (warp == 0) {
            const unsigned long long* part = g_part + b * CHUNKS_PER_B;
            unsigned long long v = 0ULL;
#pragma unroll
            for (int i = 0; i < CHUNKS_PER_B / 32; i++)
                v = max(v, part[lane + i * 32]);
#pragma unroll
            for (int o = 16; o > 0; o >>= 1) {
                unsigned long long u = __shfl_xor_sync(0xFFFFFFFFu, v, o);
                v = max(v, u);
            }
            if (lane == 0) {
                s_idx = MM - 1 - (int)(unsigned int)(v & 0xFFFFFFFFu);
                g_cnt[b] = 0;   // reset for next graph replay
            }
        }
        __syncthreads();

        const int idx = s_idx;
        const float4* src = reinterpret_cast<const float4*>(
            buffer + ((size_t)b * MM + (size_t)idx) * DD);
        float4* dst = reinterpret_cast<float4*>(out + (size_t)b * DD);
        if (threadIdx.x < DD / 4)
            dst[threadIdx.x] = src[threadIdx.x];
    }
}

extern "C" void kernel_launch(void* const* d_in, const int* in_sizes, int n_in,
                              void* d_out, int out_size)
{
    const float* inputs;
    const float* buffer;
    // inputs has BB*DD = 32768 elems, buffer has BB*MM*DD = 67108864.
    if (in_sizes[0] == BB * DD) {
        inputs = (const float*)d_in[0];
        buffer = (const float*)d_in[1];
    } else {
        inputs = (const float*)d_in[1];
        buffer = (const float*)d_in[0];
    }
    float* out = (float*)d_out;

    knn_nosync_kernel<<<BB * CHUNKS_PER_B, 256>>>(inputs, buffer, out);
}

// round 12
// speedup vs baseline: 1.0976x; 1.0976x over previous
#include <cuda_runtime.h>
#include <cstdint>

#define BB 64
#define MM 2048
#define DD 512
#define ROWS_PER_BLOCK 8
#define CHUNKS_PER_B (MM / ROWS_PER_BLOCK)   // 256
#define WARPS_PER_BLOCK 8

// Per-(batch, chunk) partial: high 32 = float bits of squared distance
// (non-negative -> monotone bit pattern), low 32 = (MM-1-idx) so ties pick the
// SMALLEST index under max (matches jnp.argmax first-occurrence).
__device__ unsigned long long g_part[BB * CHUNKS_PER_B];
// Per-batch arrival counter; zero-initialized at load, reset by the finishing
// block so every graph replay starts clean.
__device__ int g_cnt[BB];

__device__ __forceinline__ float4 ldcs4(const float4* p) {
    return __ldcs(p);   // evict-first streaming load: buffer is read-once
}

__global__ __launch_bounds__(256, 8) void knn_stream_kernel(
    const float* __restrict__ inputs,   // [BB, DD]
    const float* __restrict__ buffer,   // [BB, MM, DD]
    float* __restrict__ out)            // [BB, DD]
{
    __shared__ float4 s_in[DD / 4];                    // 2 KB query stage
    __shared__ unsigned long long s_warp_best[WARPS_PER_BLOCK];
    __shared__ int s_idx;

    const int b     = blockIdx.x >> 8;                 // / CHUNKS_PER_B
    const int chunk = blockIdx.x & (CHUNKS_PER_B - 1);

    // Stage the query row into smem (L2-resident source, coalesced).
    if (threadIdx.x < DD / 4)
        s_in[threadIdx.x] =
            reinterpret_cast<const float4*>(inputs + (size_t)b * DD)[threadIdx.x];
    __syncthreads();

    const int warp = threadIdx.x >> 5;
    const int lane = threadIdx.x & 31;
    const int m    = chunk * ROWS_PER_BLOCK + warp;    // this warp's row

    const float4* row = reinterpret_cast<const float4*>(
        buffer + ((size_t)b * MM + (size_t)m) * DD);

    // Batch all 4 row loads up front (streaming, evict-first); q comes from
    // smem at compute time so it never occupies long-lived registers.
    float4 v0 = ldcs4(row + lane);
    float4 v1 = ldcs4(row + lane + 32);
    float4 v2 = ldcs4(row + lane + 64);
    float4 v3 = ldcs4(row + lane + 96);

    float acc = 0.0f;
    {
        float4 q = s_in[lane];
        float dx = v0.x - q.x, dy = v0.y - q.y, dz = v0.z - q.z, dw = v0.w - q.w;
        acc = fmaf(dx, dx, acc); acc = fmaf(dy, dy, acc);
        acc = fmaf(dz, dz, acc); acc = fmaf(dw, dw, acc);
    }
    {
        float4 q = s_in[lane + 32];
        float dx = v1.x - q.x, dy = v1.y - q.y, dz = v1.z - q.z, dw = v1.w - q.w;
        acc = fmaf(dx, dx, acc); acc = fmaf(dy, dy, acc);
        acc = fmaf(dz, dz, acc); acc = fmaf(dw, dw, acc);
    }
    {
        float4 q = s_in[lane + 64];
        float dx = v2.x - q.x, dy = v2.y - q.y, dz = v2.z - q.z, dw = v2.w - q.w;
        acc = fmaf(dx, dx, acc); acc = fmaf(dy, dy, acc);
        acc = fmaf(dz, dz, acc); acc = fmaf(dw, dw, acc);
    }
    {
        float4 q = s_in[lane + 96];
        float dx = v3.x - q.x, dy = v3.y - q.y, dz = v3.z - q.z, dw = v3.w - q.w;
        acc = fmaf(dx, dx, acc); acc = fmaf(dy, dy, acc);
        acc = fmaf(dz, dz, acc); acc = fmaf(dw, dw, acc);
    }

    // Warp tree-reduce the row distance.
#pragma unroll
    for (int o = 16; o > 0; o >>= 1)
        acc += __shfl_xor_sync(0xFFFFFFFFu, acc, o);

    if (lane == 0) {
        s_warp_best[warp] =
            ((unsigned long long)__float_as_uint(acc) << 32) |
            (unsigned int)(MM - 1 - m);
    }
    __syncthreads();

    if (threadIdx.x == 0) {
        unsigned long long blk = 0ULL;
#pragma unroll
        for (int w = 0; w < WARPS_PER_BLOCK; w++)
            blk = max(blk, s_warp_best[w]);
        g_part[b * CHUNKS_PER_B + chunk] = blk;
        __threadfence();
        int arrived = atomicAdd(&g_cnt[b], 1);
        s_idx = (arrived == CHUNKS_PER_B - 1) ? 1 : 0;
    }
    __syncthreads();

    // Last-arriving block of this batch: reduce 256 partials + gather.
    if (s_idx) {
        if (warp == 0) {
            const unsigned long long* part = g_part + b * CHUNKS_PER_B;
            unsigned long long v = 0ULL;
#pragma unroll
            for (int i = 0; i < CHUNKS_PER_B / 32; i++)
                v = max(v, part[lane + i * 32]);
#pragma unroll
            for (int o = 16; o > 0; o >>= 1) {
                unsigned long long u = __shfl_xor_sync(0xFFFFFFFFu, v, o);
                v = max(v, u);
            }
            if (lane == 0) {
                s_idx = MM - 1 - (int)(unsigned int)(v & 0xFFFFFFFFu);
                g_cnt[b] = 0;   // reset for next graph replay
            }
        }
        __syncthreads();

        const int idx = s_idx;
        const float4* src = reinterpret_cast<const float4*>(
            buffer + ((size_t)b * MM + (size_t)idx) * DD);
        float4* dst = reinterpret_cast<float4*>(out + (size_t)b * DD);
        if (threadIdx.x < DD / 4)
            dst[threadIdx.x] = src[threadIdx.x];
    }
}

extern "C" void kernel_launch(void* const* d_in, const int* in_sizes, int n_in,
                              void* d_out, int out_size)
{
    const float* inputs;
    const float* buffer;
    // inputs has BB*DD = 32768 elems, buffer has BB*MM*DD = 67108864.
    if (in_sizes[0] == BB * DD) {
        inputs = (const float*)d_in[0];
        buffer = (const float*)d_in[1];
    } else {
        inputs = (const float*)d_in[1];
        buffer = (const float*)d_in[0];
    }
    float* out = (float*)d_out;

    knn_stream_kernel<<<BB * CHUNKS_PER_B, 256>>>(inputs, buffer, out);
}